// round 8
// baseline (speedup 1.0000x reference)
#include <cuda_runtime.h>

#define NUSERS 100000
#define NITEMS 50000
#define NNODES 150000
#define NEDGES 1200000
#define NV4    (NNODES * 16)      // float4 slots per embedding buffer
#define CHUNK  147                // scanall: elements per thread (1024*147 >= NNODES)

// Embedding buffers e0..e2 (3 x 38.4 MB) + CSR scratch. Static globals only
// (zero-initialized at module load — the zero state of g_cnt/g_pos is restored
// by kernel epilogues each call, so no separate zeroing kernel is needed).
__device__ __align__(16) float4 g_e0[NV4];
__device__ __align__(16) float4 g_e1[NV4];
__device__ __align__(16) float4 g_e2[NV4];
__device__ int  g_cnt[NNODES];          // zero at entry (static init / reorder epilogue)
__device__ int  g_pos[NNODES];          // zero at entry (static init / prop0 epilogue)
__device__ int  g_rowptr[NNODES + 1];   // full exclusive prefix
__device__ __align__(8) int2 g_edges[NEDGES];   // {col, __float_as_int(0.8*val)}

// e0 = concat(user_emb, item_emb) (streamed -> L2-warm for prop0 gathers),
// fused with the row histogram (disjoint work, g_cnt zero at entry).
__global__ __launch_bounds__(256) void k_inithist(const float* __restrict__ ue,
                                                  const float* __restrict__ ie,
                                                  const int* __restrict__ er) {
    int i = blockIdx.x * 256 + threadIdx.x;
    if (i < NEDGES) atomicAdd(&g_cnt[er[i]], 1);
    if (i >= NV4) return;
    float4 v;
    if (i < NUSERS * 16) v = ((const float4*)ue)[i];
    else                 v = ((const float4*)ie)[i - NUSERS * 16];
    g_e0[i] = v;
}

// Full exclusive scan of g_cnt -> g_rowptr in ONE kernel (one block):
// each thread serially owns CHUNK contiguous elements; block-scan of thread sums.
__global__ __launch_bounds__(1024) void k_scanall() {
    __shared__ int sh[1024];
    int t    = threadIdx.x;
    int base = t * CHUNK;
    int sum  = 0;
    for (int j = 0; j < CHUNK; j++) {
        int idx = base + j;
        if (idx < NNODES) sum += g_cnt[idx];
    }
    sh[t] = sum;
    __syncthreads();
    for (int o = 1; o < 1024; o <<= 1) {
        int x = (t >= o) ? sh[t - o] : 0;
        __syncthreads();
        sh[t] += x;
        __syncthreads();
    }
    int run = sh[t] - sum;                       // exclusive prefix of this thread
    for (int j = 0; j < CHUNK; j++) {
        int idx = base + j;
        if (idx < NNODES) { g_rowptr[idx] = run; run += g_cnt[idx]; }
    }
    if (t == 0) g_rowptr[NNODES] = NEDGES;
}

// Place each edge into its row segment (order within row arbitrary);
// epilogue re-zeroes g_cnt for the next call.
__global__ __launch_bounds__(256) void k_reorder(const int* __restrict__ er,
                                                 const int* __restrict__ ec,
                                                 const float* __restrict__ ev) {
    int e = blockIdx.x * 256 + threadIdx.x;
    if (e >= NEDGES) return;
    int row = er[e];
    int pos = g_rowptr[row] + atomicAdd(&g_pos[row], 1);
    g_edges[pos] = make_int2(ec[e], __float_as_int(ev[e] * 0.8f));
    if (e < NNODES) g_cnt[e] = 0;
}

// dst[row] = 0.2*src[row] + sum 0.8v*src[col]  -- 16 lanes per row, float4/lane.
template <int ZERO_POS>
__device__ __forceinline__ void prop_body(const float4* __restrict__ src,
                                          float4* __restrict__ dst) {
    int t = blockIdx.x * 256 + threadIdx.x;
    if (ZERO_POS && t < NNODES) g_pos[t] = 0;    // restore zero state for next call
    int row = t >> 4;
    if (row >= NNODES) return;
    int sub = t & 15;
    int beg = g_rowptr[row];
    int end = g_rowptr[row + 1];

    float4 own = src[row * 16 + sub];
    float4 s = make_float4(0.2f * own.x, 0.2f * own.y, 0.2f * own.z, 0.2f * own.w);

    int e = beg;
    for (; e + 1 < end; e += 2) {                // 2-way unroll for MLP
        int2 p0 = g_edges[e];
        int2 p1 = g_edges[e + 1];
        float4 x0 = src[p0.x * 16 + sub];
        float4 x1 = src[p1.x * 16 + sub];
        float v0 = __int_as_float(p0.y);
        float v1 = __int_as_float(p1.y);
        s.x += v0 * x0.x; s.y += v0 * x0.y; s.z += v0 * x0.z; s.w += v0 * x0.w;
        s.x += v1 * x1.x; s.y += v1 * x1.y; s.z += v1 * x1.z; s.w += v1 * x1.w;
    }
    if (e < end) {
        int2 p0 = g_edges[e];
        float4 x0 = src[p0.x * 16 + sub];
        float v0 = __int_as_float(p0.y);
        s.x += v0 * x0.x; s.y += v0 * x0.y; s.z += v0 * x0.z; s.w += v0 * x0.w;
    }
    dst[row * 16 + sub] = s;
}

__global__ __launch_bounds__(256) void k_prop0() { prop_body<1>(g_e0, g_e1); }
__global__ __launch_bounds__(256) void k_prop1() { prop_body<0>(g_e1, g_e2); }

// acc(n) = e0+e1+e2+e3, e3 computed on the fly from e2 (only 8192 nodes need it).
__device__ __forceinline__ float2 node_acc(int n, int lane) {
    const float2* __restrict__ E0 = (const float2*)g_e0;
    const float2* __restrict__ E1 = (const float2*)g_e1;
    const float2* __restrict__ E2 = (const float2*)g_e2;
    float2 z0 = E0[n * 32 + lane];
    float2 z1 = E1[n * 32 + lane];
    float2 z2 = E2[n * 32 + lane];
    float2 z3 = make_float2(0.2f * z2.x, 0.2f * z2.y);
    int beg = g_rowptr[n];
    int end = g_rowptr[n + 1];
    int e = beg;
    for (; e + 1 < end; e += 2) {
        int2 p0 = g_edges[e];
        int2 p1 = g_edges[e + 1];
        float2 x0 = E2[p0.x * 32 + lane];
        float2 x1 = E2[p1.x * 32 + lane];
        float v0 = __int_as_float(p0.y);
        float v1 = __int_as_float(p1.y);
        z3.x += v0 * x0.x; z3.y += v0 * x0.y;
        z3.x += v1 * x1.x; z3.y += v1 * x1.y;
    }
    if (e < end) {
        int2 p0 = g_edges[e];
        float2 x0 = E2[p0.x * 32 + lane];
        float v0 = __int_as_float(p0.y);
        z3.x += v0 * x0.x; z3.y += v0 * x0.y;
    }
    return make_float2(z0.x + z1.x + z2.x + z3.x, z0.y + z1.y + z2.y + z3.y);
}

// gamma[w] = dot(acc(u), acc(NUSERS+i)) / 16
__global__ __launch_bounds__(256) void k_gamma(const int* __restrict__ users,
                                               const int* __restrict__ items,
                                               float* __restrict__ out) {
    int w    = (blockIdx.x * 256 + threadIdx.x) >> 5;   // warp per output pair
    int lane = threadIdx.x & 31;
    if (w >= 4096) return;
    float2 a = node_acc(users[w],          lane);
    float2 b = node_acc(NUSERS + items[w], lane);
    float s = a.x * b.x + a.y * b.y;
    #pragma unroll
    for (int o = 16; o; o >>= 1) s += __shfl_xor_sync(0xffffffffu, s, o);
    if (lane == 0) out[w] = s * (1.0f / 16.0f);
}

extern "C" void kernel_launch(void* const* d_in, const int* in_sizes, int n_in,
                              void* d_out, int out_size) {
    const int*   users = (const int*)  d_in[0];
    const int*   items = (const int*)  d_in[1];
    const int*   er    = (const int*)  d_in[2];
    const int*   ec    = (const int*)  d_in[3];
    const float* ev    = (const float*)d_in[4];
    const float* ue    = (const float*)d_in[5];
    const float* ie    = (const float*)d_in[6];
    float* out = (float*)d_out;

    const int PROP_BLOCKS = (NV4 + 255) / 256;        // 9375 (16 lanes/row)
    const int EDGE_BLOCKS = (NEDGES + 255) / 256;     // 4688

    k_inithist<<<PROP_BLOCKS, 256>>>(ue, ie, er);     // covers NV4 >= NEDGES threads
    k_scanall<<<1, 1024>>>();
    k_reorder<<<EDGE_BLOCKS, 256>>>(er, ec, ev);
    k_prop0<<<PROP_BLOCKS, 256>>>();                  // our launch #3 -> ncu capture
    k_prop1<<<PROP_BLOCKS, 256>>>();
    k_gamma<<<4096 / 8, 256>>>(users, items, out);
}

// round 9
// speedup vs baseline: 2.1111x; 2.1111x over previous
#include <cuda_runtime.h>

#define NUSERS 100000
#define NITEMS 50000
#define NNODES 150000
#define NEDGES 1200000
#define NV4    (NNODES * 16)        // float4 slots per embedding buffer
#define SCAN_B 1024
#define NBLK   ((NNODES + SCAN_B - 1) / SCAN_B)   // 147

// Embedding buffers e0..e2 (3 x 38.4 MB) + CSR scratch. Static globals only.
// g_cnt/g_pos zero at entry: static init on first call, restored by kernel
// epilogues on every call (reorder zeroes g_cnt, prop0 zeroes g_pos).
__device__ __align__(16) float4 g_e0[NV4];
__device__ __align__(16) float4 g_e1[NV4];
__device__ __align__(16) float4 g_e2[NV4];
__device__ int  g_cnt[NNODES];
__device__ int  g_pos[NNODES];
__device__ int  g_rowptr[NNODES + 1];   // block-local exclusive prefix (add g_bsum)
__device__ int  g_bsum[NBLK];           // exclusive prefix of per-block totals
__device__ __align__(8) int2 g_edges[NEDGES];   // {col, __float_as_int(0.8*val)}

// e0 = concat(user_emb, item_emb) (streamed -> L2-warm for prop0 gathers),
// fused with the row histogram (disjoint work, g_cnt zero at entry).
__global__ __launch_bounds__(256) void k_inithist(const float* __restrict__ ue,
                                                  const float* __restrict__ ie,
                                                  const int* __restrict__ er) {
    int i = blockIdx.x * 256 + threadIdx.x;
    if (i < NEDGES) atomicAdd(&g_cnt[er[i]], 1);
    if (i >= NV4) return;
    float4 v;
    if (i < NUSERS * 16) v = ((const float4*)ue)[i];
    else                 v = ((const float4*)ie)[i - NUSERS * 16];
    g_e0[i] = v;
}

// Per-block COALESCED exclusive scan of g_cnt -> g_rowptr; block totals -> g_bsum.
__global__ __launch_bounds__(SCAN_B) void k_scan1() {
    __shared__ int sh[SCAN_B];
    int idx = blockIdx.x * SCAN_B + threadIdx.x;
    int v = (idx < NNODES) ? g_cnt[idx] : 0;
    sh[threadIdx.x] = v;
    __syncthreads();
    #pragma unroll
    for (int o = 1; o < SCAN_B; o <<= 1) {
        int t = (threadIdx.x >= o) ? sh[threadIdx.x - o] : 0;
        __syncthreads();
        sh[threadIdx.x] += t;
        __syncthreads();
    }
    int incl = sh[threadIdx.x];
    if (idx <= NNODES) g_rowptr[idx] = incl - v;               // block-local exclusive
    if (threadIdx.x == SCAN_B - 1) g_bsum[blockIdx.x] = incl;  // block total
}

// Parallel exclusive scan of the 147 block totals (one block, Hillis-Steele).
__global__ __launch_bounds__(256) void k_scan2() {
    __shared__ int sh[256];
    int i = threadIdx.x;
    int v = (i < NBLK) ? g_bsum[i] : 0;
    sh[i] = v;
    __syncthreads();
    #pragma unroll
    for (int o = 1; o < 256; o <<= 1) {
        int t = (i >= o) ? sh[i - o] : 0;
        __syncthreads();
        sh[i] += t;
        __syncthreads();
    }
    if (i < NBLK) g_bsum[i] = sh[i] - v;                       // exclusive
}

__device__ __forceinline__ void row_range(int row, int& beg, int& end) {
    beg = g_rowptr[row]     + g_bsum[row >> 10];
    end = g_rowptr[row + 1] + g_bsum[(row + 1) >> 10];
}

// Place each edge into its row segment; epilogue re-zeroes g_cnt for next call.
__global__ __launch_bounds__(256) void k_reorder(const int* __restrict__ er,
                                                 const int* __restrict__ ec,
                                                 const float* __restrict__ ev) {
    int e = blockIdx.x * 256 + threadIdx.x;
    if (e >= NEDGES) return;
    int row  = er[e];
    int base = g_rowptr[row] + g_bsum[row >> 10];
    int pos  = base + atomicAdd(&g_pos[row], 1);
    g_edges[pos] = make_int2(ec[e], __float_as_int(ev[e] * 0.8f));
    if (e < NNODES) g_cnt[e] = 0;
}

// dst[row] = 0.2*src[row] + sum 0.8v*src[col]  -- 16 lanes/row, float4/lane,
// 4-way unrolled edge loop for MLP (prop is latency-bound per ncu).
template <int ZERO_POS>
__device__ __forceinline__ void prop_body(const float4* __restrict__ src,
                                          float4* __restrict__ dst) {
    int t = blockIdx.x * 256 + threadIdx.x;
    if (ZERO_POS && t < NNODES) g_pos[t] = 0;   // restore zero state for next call
    int row = t >> 4;
    if (row >= NNODES) return;
    int sub = t & 15;
    int beg, end; row_range(row, beg, end);

    float4 own = src[row * 16 + sub];
    float4 s = make_float4(0.2f * own.x, 0.2f * own.y, 0.2f * own.z, 0.2f * own.w);

    int e  = beg;
    int n4 = beg + ((end - beg) & ~3);
    for (; e < n4; e += 4) {
        int2 p0 = g_edges[e];
        int2 p1 = g_edges[e + 1];
        int2 p2 = g_edges[e + 2];
        int2 p3 = g_edges[e + 3];
        float4 x0 = src[p0.x * 16 + sub];
        float4 x1 = src[p1.x * 16 + sub];
        float4 x2 = src[p2.x * 16 + sub];
        float4 x3 = src[p3.x * 16 + sub];
        float v0 = __int_as_float(p0.y);
        float v1 = __int_as_float(p1.y);
        float v2 = __int_as_float(p2.y);
        float v3 = __int_as_float(p3.y);
        s.x += v0 * x0.x; s.y += v0 * x0.y; s.z += v0 * x0.z; s.w += v0 * x0.w;
        s.x += v1 * x1.x; s.y += v1 * x1.y; s.z += v1 * x1.z; s.w += v1 * x1.w;
        s.x += v2 * x2.x; s.y += v2 * x2.y; s.z += v2 * x2.z; s.w += v2 * x2.w;
        s.x += v3 * x3.x; s.y += v3 * x3.y; s.z += v3 * x3.z; s.w += v3 * x3.w;
    }
    for (; e < end; e++) {
        int2 p0 = g_edges[e];
        float4 x0 = src[p0.x * 16 + sub];
        float v0 = __int_as_float(p0.y);
        s.x += v0 * x0.x; s.y += v0 * x0.y; s.z += v0 * x0.z; s.w += v0 * x0.w;
    }
    dst[row * 16 + sub] = s;
}

__global__ __launch_bounds__(256) void k_prop0() { prop_body<1>(g_e0, g_e1); }
__global__ __launch_bounds__(256) void k_prop1() { prop_body<0>(g_e1, g_e2); }

// acc(n) = e0+e1+e2+e3, e3 computed on the fly from e2 (only 8192 nodes need it).
__device__ __forceinline__ float2 node_acc(int n, int lane) {
    const float2* __restrict__ E0 = (const float2*)g_e0;
    const float2* __restrict__ E1 = (const float2*)g_e1;
    const float2* __restrict__ E2 = (const float2*)g_e2;
    float2 z0 = E0[n * 32 + lane];
    float2 z1 = E1[n * 32 + lane];
    float2 z2 = E2[n * 32 + lane];
    float2 z3 = make_float2(0.2f * z2.x, 0.2f * z2.y);
    int beg, end; row_range(n, beg, end);
    int e  = beg;
    int n4 = beg + ((end - beg) & ~3);
    for (; e < n4; e += 4) {
        int2 p0 = g_edges[e];
        int2 p1 = g_edges[e + 1];
        int2 p2 = g_edges[e + 2];
        int2 p3 = g_edges[e + 3];
        float2 x0 = E2[p0.x * 32 + lane];
        float2 x1 = E2[p1.x * 32 + lane];
        float2 x2 = E2[p2.x * 32 + lane];
        float2 x3 = E2[p3.x * 32 + lane];
        z3.x += __int_as_float(p0.y) * x0.x; z3.y += __int_as_float(p0.y) * x0.y;
        z3.x += __int_as_float(p1.y) * x1.x; z3.y += __int_as_float(p1.y) * x1.y;
        z3.x += __int_as_float(p2.y) * x2.x; z3.y += __int_as_float(p2.y) * x2.y;
        z3.x += __int_as_float(p3.y) * x3.x; z3.y += __int_as_float(p3.y) * x3.y;
    }
    for (; e < end; e++) {
        int2 p0 = g_edges[e];
        float2 x0 = E2[p0.x * 32 + lane];
        float v0 = __int_as_float(p0.y);
        z3.x += v0 * x0.x; z3.y += v0 * x0.y;
    }
    return make_float2(z0.x + z1.x + z2.x + z3.x, z0.y + z1.y + z2.y + z3.y);
}

// gamma[w] = dot(acc(u), acc(NUSERS+i)) / 16
__global__ __launch_bounds__(256) void k_gamma(const int* __restrict__ users,
                                               const int* __restrict__ items,
                                               float* __restrict__ out) {
    int w    = (blockIdx.x * 256 + threadIdx.x) >> 5;   // warp per output pair
    int lane = threadIdx.x & 31;
    if (w >= 4096) return;
    float2 a = node_acc(users[w],          lane);
    float2 b = node_acc(NUSERS + items[w], lane);
    float s = a.x * b.x + a.y * b.y;
    #pragma unroll
    for (int o = 16; o; o >>= 1) s += __shfl_xor_sync(0xffffffffu, s, o);
    if (lane == 0) out[w] = s * (1.0f / 16.0f);
}

extern "C" void kernel_launch(void* const* d_in, const int* in_sizes, int n_in,
                              void* d_out, int out_size) {
    const int*   users = (const int*)  d_in[0];
    const int*   items = (const int*)  d_in[1];
    const int*   er    = (const int*)  d_in[2];
    const int*   ec    = (const int*)  d_in[3];
    const float* ev    = (const float*)d_in[4];
    const float* ue    = (const float*)d_in[5];
    const float* ie    = (const float*)d_in[6];
    float* out = (float*)d_out;

    const int PROP_BLOCKS = (NV4 + 255) / 256;        // 9375 (16 lanes/row)
    const int EDGE_BLOCKS = (NEDGES + 255) / 256;     // 4688

    k_inithist<<<PROP_BLOCKS, 256>>>(ue, ie, er);     // covers NV4 >= NEDGES threads
    k_scan1<<<NBLK, SCAN_B>>>();
    k_scan2<<<1, 256>>>();
    k_reorder<<<EDGE_BLOCKS, 256>>>(er, ec, ev);
    k_prop0<<<PROP_BLOCKS, 256>>>();
    k_prop1<<<PROP_BLOCKS, 256>>>();
    k_gamma<<<4096 / 8, 256>>>(users, items, out);
}

// round 10
// speedup vs baseline: 2.1648x; 1.0254x over previous
#include <cuda_runtime.h>

#define NUSERS 100000
#define NITEMS 50000
#define NNODES 150000
#define NEDGES 1200000
#define NV4    (NNODES * 16)        // float4 slots per embedding buffer
#define SCAN_B 1024
#define NBLK   ((NNODES + SCAN_B - 1) / SCAN_B)   // 147

// Embedding buffers e0..e2 (3 x 38.4 MB) + CSR scratch. Static globals only.
// Zero-state protocol (restored every call): g_cnt zeroed by reorder epilogue,
// g_pos by prop0 epilogue, g_done by scan1's finalizer block.
__device__ __align__(16) float4 g_e0[NV4];
__device__ __align__(16) float4 g_e1[NV4];
__device__ __align__(16) float4 g_e2[NV4];
__device__ int  g_cnt[NNODES];
__device__ int  g_pos[NNODES];
__device__ int  g_rowptr[NNODES + 1];   // block-local exclusive prefix (add g_bsum)
__device__ int  g_bsum[NBLK];           // exclusive prefix of per-block totals
__device__ int  g_done;                 // scan1 completion counter
__device__ __align__(8) int2 g_edges[NEDGES];   // {col, __float_as_int(0.8*val)}

// e0 = concat(user_emb, item_emb) (streamed -> L2-warm for prop0 gathers),
// fused with the row histogram (disjoint work, g_cnt zero at entry).
__global__ __launch_bounds__(256) void k_inithist(const float* __restrict__ ue,
                                                  const float* __restrict__ ie,
                                                  const int* __restrict__ er) {
    int i = blockIdx.x * 256 + threadIdx.x;
    if (i < NEDGES) atomicAdd(&g_cnt[er[i]], 1);
    if (i >= NV4) return;
    float4 v;
    if (i < NUSERS * 16) v = ((const float4*)ue)[i];
    else                 v = ((const float4*)ie)[i - NUSERS * 16];
    g_e0[i] = v;
}

// Coalesced per-block exclusive scan of g_cnt -> g_rowptr; block totals -> g_bsum.
// Last-arriving block converts g_bsum to an exclusive prefix (fused "scan2").
__global__ __launch_bounds__(SCAN_B) void k_scan1() {
    __shared__ int sh[SCAN_B];
    __shared__ int s_last;
    int idx = blockIdx.x * SCAN_B + threadIdx.x;
    int v = (idx < NNODES) ? g_cnt[idx] : 0;
    sh[threadIdx.x] = v;
    __syncthreads();
    #pragma unroll
    for (int o = 1; o < SCAN_B; o <<= 1) {
        int t = (threadIdx.x >= o) ? sh[threadIdx.x - o] : 0;
        __syncthreads();
        sh[threadIdx.x] += t;
        __syncthreads();
    }
    int incl = sh[threadIdx.x];
    if (idx <= NNODES) g_rowptr[idx] = incl - v;               // block-local exclusive
    if (threadIdx.x == SCAN_B - 1) g_bsum[blockIdx.x] = incl;  // block total

    // Completion handshake: the last block to finish scans g_bsum in place.
    __threadfence();
    if (threadIdx.x == 0) s_last = (atomicAdd(&g_done, 1) == NBLK - 1);
    __syncthreads();
    if (s_last) {
        int i = threadIdx.x;
        int bv = (i < NBLK) ? g_bsum[i] : 0;
        sh[i] = bv;
        __syncthreads();
        #pragma unroll
        for (int o = 1; o < SCAN_B; o <<= 1) {
            int t = (i >= o) ? sh[i - o] : 0;
            __syncthreads();
            sh[i] += t;
            __syncthreads();
        }
        if (i < NBLK) g_bsum[i] = sh[i] - bv;                  // exclusive
        if (i == 0) g_done = 0;                                // restore zero state
    }
}

__device__ __forceinline__ void row_range(int row, int& beg, int& end) {
    beg = g_rowptr[row]     + g_bsum[row >> 10];
    end = g_rowptr[row + 1] + g_bsum[(row + 1) >> 10];
}

// Place edges into row segments, 4 edges/thread (independent chains for MLP);
// epilogue re-zeroes g_cnt for the next call.
__global__ __launch_bounds__(256) void k_reorder(const int* __restrict__ er,
                                                 const int* __restrict__ ec,
                                                 const float* __restrict__ ev) {
    int t = blockIdx.x * 256 + threadIdx.x;
    int b = blockIdx.x * 1024 + threadIdx.x;       // block owns 1024 edges
    #pragma unroll
    for (int j = 0; j < 4; j++) {
        int e = b + j * 256;
        if (e < NEDGES) {
            int row  = er[e];
            int base = g_rowptr[row] + g_bsum[row >> 10];
            int pos  = base + atomicAdd(&g_pos[row], 1);
            g_edges[pos] = make_int2(ec[e], __float_as_int(ev[e] * 0.8f));
        }
    }
    if (t < NNODES) g_cnt[t] = 0;                  // grid 300k threads >= NNODES
}

// dst[row] = 0.2*src[row] + sum 0.8v*src[col]
// 8 lanes/row, 2 consecutive float4 per lane, 4-edge unroll -> 8 gathers in flight.
template <int ZERO_POS>
__device__ __forceinline__ void prop_body(const float4* __restrict__ src,
                                          float4* __restrict__ dst) {
    int t = blockIdx.x * 256 + threadIdx.x;        // NNODES*8 = 1.2M threads
    if (ZERO_POS && t < NNODES) g_pos[t] = 0;      // restore zero state
    int row = t >> 3;
    if (row >= NNODES) return;
    int sub  = (t & 7) * 2;                        // float4 pair: sub, sub+1
    int base = row * 16 + sub;
    int beg, end; row_range(row, beg, end);

    float4 o0 = src[base], o1 = src[base + 1];
    float4 s0 = make_float4(0.2f * o0.x, 0.2f * o0.y, 0.2f * o0.z, 0.2f * o0.w);
    float4 s1 = make_float4(0.2f * o1.x, 0.2f * o1.y, 0.2f * o1.z, 0.2f * o1.w);

    int e  = beg;
    int n4 = beg + ((end - beg) & ~3);
    for (; e < n4; e += 4) {
        int2 p0 = g_edges[e];
        int2 p1 = g_edges[e + 1];
        int2 p2 = g_edges[e + 2];
        int2 p3 = g_edges[e + 3];
        int c0 = p0.x * 16 + sub, c1 = p1.x * 16 + sub;
        int c2 = p2.x * 16 + sub, c3 = p3.x * 16 + sub;
        float4 a0 = src[c0], b0 = src[c0 + 1];
        float4 a1 = src[c1], b1 = src[c1 + 1];
        float4 a2 = src[c2], b2 = src[c2 + 1];
        float4 a3 = src[c3], b3 = src[c3 + 1];
        float v0 = __int_as_float(p0.y);
        float v1 = __int_as_float(p1.y);
        float v2 = __int_as_float(p2.y);
        float v3 = __int_as_float(p3.y);
        s0.x += v0 * a0.x; s0.y += v0 * a0.y; s0.z += v0 * a0.z; s0.w += v0 * a0.w;
        s1.x += v0 * b0.x; s1.y += v0 * b0.y; s1.z += v0 * b0.z; s1.w += v0 * b0.w;
        s0.x += v1 * a1.x; s0.y += v1 * a1.y; s0.z += v1 * a1.z; s0.w += v1 * a1.w;
        s1.x += v1 * b1.x; s1.y += v1 * b1.y; s1.z += v1 * b1.z; s1.w += v1 * b1.w;
        s0.x += v2 * a2.x; s0.y += v2 * a2.y; s0.z += v2 * a2.z; s0.w += v2 * a2.w;
        s1.x += v2 * b2.x; s1.y += v2 * b2.y; s1.z += v2 * b2.z; s1.w += v2 * b2.w;
        s0.x += v3 * a3.x; s0.y += v3 * a3.y; s0.z += v3 * a3.z; s0.w += v3 * a3.w;
        s1.x += v3 * b3.x; s1.y += v3 * b3.y; s1.z += v3 * b3.z; s1.w += v3 * b3.w;
    }
    for (; e < end; e++) {
        int2 p = g_edges[e];
        int c  = p.x * 16 + sub;
        float4 a = src[c], b = src[c + 1];
        float v = __int_as_float(p.y);
        s0.x += v * a.x; s0.y += v * a.y; s0.z += v * a.z; s0.w += v * a.w;
        s1.x += v * b.x; s1.y += v * b.y; s1.z += v * b.z; s1.w += v * b.w;
    }
    dst[base]     = s0;
    dst[base + 1] = s1;
}

__global__ __launch_bounds__(256) void k_prop0() { prop_body<1>(g_e0, g_e1); }
__global__ __launch_bounds__(256) void k_prop1() { prop_body<0>(g_e1, g_e2); }

// acc(n) = e0+e1+e2+e3, e3 computed on the fly from e2 (only 8192 nodes need it).
__device__ __forceinline__ float2 node_acc(int n, int lane) {
    const float2* __restrict__ E0 = (const float2*)g_e0;
    const float2* __restrict__ E1 = (const float2*)g_e1;
    const float2* __restrict__ E2 = (const float2*)g_e2;
    float2 z0 = E0[n * 32 + lane];
    float2 z1 = E1[n * 32 + lane];
    float2 z2 = E2[n * 32 + lane];
    float2 z3 = make_float2(0.2f * z2.x, 0.2f * z2.y);
    int beg, end; row_range(n, beg, end);
    int e  = beg;
    int n4 = beg + ((end - beg) & ~3);
    for (; e < n4; e += 4) {
        int2 p0 = g_edges[e];
        int2 p1 = g_edges[e + 1];
        int2 p2 = g_edges[e + 2];
        int2 p3 = g_edges[e + 3];
        float2 x0 = E2[p0.x * 32 + lane];
        float2 x1 = E2[p1.x * 32 + lane];
        float2 x2 = E2[p2.x * 32 + lane];
        float2 x3 = E2[p3.x * 32 + lane];
        z3.x += __int_as_float(p0.y) * x0.x; z3.y += __int_as_float(p0.y) * x0.y;
        z3.x += __int_as_float(p1.y) * x1.x; z3.y += __int_as_float(p1.y) * x1.y;
        z3.x += __int_as_float(p2.y) * x2.x; z3.y += __int_as_float(p2.y) * x2.y;
        z3.x += __int_as_float(p3.y) * x3.x; z3.y += __int_as_float(p3.y) * x3.y;
    }
    for (; e < end; e++) {
        int2 p = g_edges[e];
        float2 x = E2[p.x * 32 + lane];
        float v = __int_as_float(p.y);
        z3.x += v * x.x; z3.y += v * x.y;
    }
    return make_float2(z0.x + z1.x + z2.x + z3.x, z0.y + z1.y + z2.y + z3.y);
}

// gamma[w] = dot(acc(u), acc(NUSERS+i)) / 16
__global__ __launch_bounds__(256) void k_gamma(const int* __restrict__ users,
                                               const int* __restrict__ items,
                                               float* __restrict__ out) {
    int w    = (blockIdx.x * 256 + threadIdx.x) >> 5;   // warp per output pair
    int lane = threadIdx.x & 31;
    if (w >= 4096) return;
    float2 a = node_acc(users[w],          lane);
    float2 b = node_acc(NUSERS + items[w], lane);
    float s = a.x * b.x + a.y * b.y;
    #pragma unroll
    for (int o = 16; o; o >>= 1) s += __shfl_xor_sync(0xffffffffu, s, o);
    if (lane == 0) out[w] = s * (1.0f / 16.0f);
}

extern "C" void kernel_launch(void* const* d_in, const int* in_sizes, int n_in,
                              void* d_out, int out_size) {
    const int*   users = (const int*)  d_in[0];
    const int*   items = (const int*)  d_in[1];
    const int*   er    = (const int*)  d_in[2];
    const int*   ec    = (const int*)  d_in[3];
    const float* ev    = (const float*)d_in[4];
    const float* ue    = (const float*)d_in[5];
    const float* ie    = (const float*)d_in[6];
    float* out = (float*)d_out;

    const int INIT_BLOCKS = (NV4 + 255) / 256;            // 9375
    const int PROP_BLOCKS = (NNODES * 8 + 255) / 256;     // 4688 (8 lanes/row)
    const int REO_BLOCKS  = (NEDGES + 1023) / 1024;       // 1172 (4 edges/thread)

    k_inithist<<<INIT_BLOCKS, 256>>>(ue, ie, er);
    k_scan1<<<NBLK, SCAN_B>>>();                          // scan2 fused (last block)
    k_reorder<<<REO_BLOCKS, 256>>>(er, ec, ev);
    k_prop0<<<PROP_BLOCKS, 256>>>();                      // captured by ncu (-s5 -c1)
    k_prop1<<<PROP_BLOCKS, 256>>>();
    k_gamma<<<4096 / 8, 256>>>(users, items, out);
}

// round 11
// speedup vs baseline: 2.2857x; 1.0559x over previous
#include <cuda_runtime.h>

#define NUSERS 100000
#define NITEMS 50000
#define NNODES 150000
#define NEDGES 1200000
#define NV4    (NNODES * 16)        // float4 slots per embedding buffer
#define SCAN_B 1024
#define NBLK   ((NNODES + SCAN_B - 1) / SCAN_B)   // 147

// Embedding buffers e0..e2 (3 x 38.4 MB) + CSR scratch. Static globals only.
// Zero-state protocol (restored every call): g_cnt zeroed by reorder epilogue,
// g_pos by prop0 epilogue, g_done by scan1's finalizer block.
__device__ __align__(16) float4 g_e0[NV4];
__device__ __align__(16) float4 g_e1[NV4];
__device__ __align__(16) float4 g_e2[NV4];
__device__ int  g_cnt[NNODES];
__device__ int  g_pos[NNODES];
__device__ int  g_rowptr[NNODES + 1];   // block-local exclusive prefix (add g_bsum)
__device__ int  g_bsum[NBLK];           // exclusive prefix of per-block totals
__device__ int  g_done;                 // scan1 completion counter
__device__ __align__(8) int2 g_edges[NEDGES];   // {col, __float_as_int(0.8*val)}

// e0 = concat(user_emb, item_emb) (streamed -> L2-warm for prop0 gathers),
// fused with the row histogram (disjoint work, g_cnt zero at entry).
__global__ __launch_bounds__(256) void k_inithist(const float* __restrict__ ue,
                                                  const float* __restrict__ ie,
                                                  const int* __restrict__ er) {
    int i = blockIdx.x * 256 + threadIdx.x;
    if (i < NEDGES) atomicAdd(&g_cnt[er[i]], 1);
    if (i >= NV4) return;
    float4 v;
    if (i < NUSERS * 16) v = ((const float4*)ue)[i];
    else                 v = ((const float4*)ie)[i - NUSERS * 16];
    g_e0[i] = v;
}

// Coalesced per-block exclusive scan of g_cnt -> g_rowptr; block totals -> g_bsum.
// Last-arriving block converts g_bsum to an exclusive prefix (fused "scan2").
__global__ __launch_bounds__(SCAN_B) void k_scan1() {
    __shared__ int sh[SCAN_B];
    __shared__ int s_last;
    int idx = blockIdx.x * SCAN_B + threadIdx.x;
    int v = (idx < NNODES) ? g_cnt[idx] : 0;
    sh[threadIdx.x] = v;
    __syncthreads();
    #pragma unroll
    for (int o = 1; o < SCAN_B; o <<= 1) {
        int t = (threadIdx.x >= o) ? sh[threadIdx.x - o] : 0;
        __syncthreads();
        sh[threadIdx.x] += t;
        __syncthreads();
    }
    int incl = sh[threadIdx.x];
    if (idx <= NNODES) g_rowptr[idx] = incl - v;               // block-local exclusive
    if (threadIdx.x == SCAN_B - 1) g_bsum[blockIdx.x] = incl;  // block total

    // Completion handshake: the last block to finish scans g_bsum in place.
    __threadfence();
    if (threadIdx.x == 0) s_last = (atomicAdd(&g_done, 1) == NBLK - 1);
    __syncthreads();
    if (s_last) {
        int i = threadIdx.x;
        int bv = (i < NBLK) ? g_bsum[i] : 0;
        sh[i] = bv;
        __syncthreads();
        #pragma unroll
        for (int o = 1; o < SCAN_B; o <<= 1) {
            int t = (i >= o) ? sh[i - o] : 0;
            __syncthreads();
            sh[i] += t;
            __syncthreads();
        }
        if (i < NBLK) g_bsum[i] = sh[i] - bv;                  // exclusive
        if (i == 0) g_done = 0;                                // restore zero state
    }
}

__device__ __forceinline__ void row_range(int row, int& beg, int& end) {
    beg = g_rowptr[row]     + g_bsum[row >> 10];
    end = g_rowptr[row + 1] + g_bsum[(row + 1) >> 10];
}

// Place edges into row segments, 4 edges/thread (independent chains for MLP);
// epilogue re-zeroes g_cnt for the next call.
__global__ __launch_bounds__(256) void k_reorder(const int* __restrict__ er,
                                                 const int* __restrict__ ec,
                                                 const float* __restrict__ ev) {
    int t = blockIdx.x * 256 + threadIdx.x;
    int b = blockIdx.x * 1024 + threadIdx.x;       // block owns 1024 edges
    #pragma unroll
    for (int j = 0; j < 4; j++) {
        int e = b + j * 256;
        if (e < NEDGES) {
            int row  = er[e];
            int base = g_rowptr[row] + g_bsum[row >> 10];
            int pos  = base + atomicAdd(&g_pos[row], 1);
            g_edges[pos] = make_int2(ec[e], __float_as_int(ev[e] * 0.8f));
        }
    }
    if (t < NNODES) g_cnt[t] = 0;                  // grid 300k threads >= NNODES
}

// dst[row] = 0.2*src[row] + sum 0.8v*src[col]
// 8 lanes/row, each lane owns float4 slots {sub, sub+8} -> BOTH loads are dense
// 128B segments per 8-lane group (fixes round-10's stride-32B wavefront blowup),
// 4-edge unroll keeps 8 independent gathers in flight per thread.
template <int ZERO_POS>
__device__ __forceinline__ void prop_body(const float4* __restrict__ src,
                                          float4* __restrict__ dst) {
    int t = blockIdx.x * 256 + threadIdx.x;        // NNODES*8 = 1.2M threads
    if (ZERO_POS && t < NNODES) g_pos[t] = 0;      // restore zero state
    int row = t >> 3;
    if (row >= NNODES) return;
    int sub  = t & 7;                              // slots: sub and sub+8
    int base = row * 16 + sub;
    int beg, end; row_range(row, beg, end);

    float4 o0 = src[base], o1 = src[base + 8];
    float4 s0 = make_float4(0.2f * o0.x, 0.2f * o0.y, 0.2f * o0.z, 0.2f * o0.w);
    float4 s1 = make_float4(0.2f * o1.x, 0.2f * o1.y, 0.2f * o1.z, 0.2f * o1.w);

    int e  = beg;
    int n4 = beg + ((end - beg) & ~3);
    for (; e < n4; e += 4) {
        int2 p0 = g_edges[e];
        int2 p1 = g_edges[e + 1];
        int2 p2 = g_edges[e + 2];
        int2 p3 = g_edges[e + 3];
        int c0 = p0.x * 16 + sub, c1 = p1.x * 16 + sub;
        int c2 = p2.x * 16 + sub, c3 = p3.x * 16 + sub;
        float4 a0 = src[c0], b0 = src[c0 + 8];
        float4 a1 = src[c1], b1 = src[c1 + 8];
        float4 a2 = src[c2], b2 = src[c2 + 8];
        float4 a3 = src[c3], b3 = src[c3 + 8];
        float v0 = __int_as_float(p0.y);
        float v1 = __int_as_float(p1.y);
        float v2 = __int_as_float(p2.y);
        float v3 = __int_as_float(p3.y);
        s0.x += v0 * a0.x; s0.y += v0 * a0.y; s0.z += v0 * a0.z; s0.w += v0 * a0.w;
        s1.x += v0 * b0.x; s1.y += v0 * b0.y; s1.z += v0 * b0.z; s1.w += v0 * b0.w;
        s0.x += v1 * a1.x; s0.y += v1 * a1.y; s0.z += v1 * a1.z; s0.w += v1 * a1.w;
        s1.x += v1 * b1.x; s1.y += v1 * b1.y; s1.z += v1 * b1.z; s1.w += v1 * b1.w;
        s0.x += v2 * a2.x; s0.y += v2 * a2.y; s0.z += v2 * a2.z; s0.w += v2 * a2.w;
        s1.x += v2 * b2.x; s1.y += v2 * b2.y; s1.z += v2 * b2.z; s1.w += v2 * b2.w;
        s0.x += v3 * a3.x; s0.y += v3 * a3.y; s0.z += v3 * a3.z; s0.w += v3 * a3.w;
        s1.x += v3 * b3.x; s1.y += v3 * b3.y; s1.z += v3 * b3.z; s1.w += v3 * b3.w;
    }
    for (; e < end; e++) {
        int2 p = g_edges[e];
        int c  = p.x * 16 + sub;
        float4 a = src[c], b = src[c + 8];
        float v = __int_as_float(p.y);
        s0.x += v * a.x; s0.y += v * a.y; s0.z += v * a.z; s0.w += v * a.w;
        s1.x += v * b.x; s1.y += v * b.y; s1.z += v * b.z; s1.w += v * b.w;
    }
    dst[base]     = s0;
    dst[base + 8] = s1;
}

__global__ __launch_bounds__(256) void k_prop0() { prop_body<1>(g_e0, g_e1); }
__global__ __launch_bounds__(256) void k_prop1() { prop_body<0>(g_e1, g_e2); }

// acc(n) = e0+e1+e2+e3, e3 computed on the fly from e2 (only 8192 nodes need it).
__device__ __forceinline__ float2 node_acc(int n, int lane) {
    const float2* __restrict__ E0 = (const float2*)g_e0;
    const float2* __restrict__ E1 = (const float2*)g_e1;
    const float2* __restrict__ E2 = (const float2*)g_e2;
    float2 z0 = E0[n * 32 + lane];
    float2 z1 = E1[n * 32 + lane];
    float2 z2 = E2[n * 32 + lane];
    float2 z3 = make_float2(0.2f * z2.x, 0.2f * z2.y);
    int beg, end; row_range(n, beg, end);
    int e  = beg;
    int n4 = beg + ((end - beg) & ~3);
    for (; e < n4; e += 4) {
        int2 p0 = g_edges[e];
        int2 p1 = g_edges[e + 1];
        int2 p2 = g_edges[e + 2];
        int2 p3 = g_edges[e + 3];
        float2 x0 = E2[p0.x * 32 + lane];
        float2 x1 = E2[p1.x * 32 + lane];
        float2 x2 = E2[p2.x * 32 + lane];
        float2 x3 = E2[p3.x * 32 + lane];
        z3.x += __int_as_float(p0.y) * x0.x; z3.y += __int_as_float(p0.y) * x0.y;
        z3.x += __int_as_float(p1.y) * x1.x; z3.y += __int_as_float(p1.y) * x1.y;
        z3.x += __int_as_float(p2.y) * x2.x; z3.y += __int_as_float(p2.y) * x2.y;
        z3.x += __int_as_float(p3.y) * x3.x; z3.y += __int_as_float(p3.y) * x3.y;
    }
    for (; e < end; e++) {
        int2 p = g_edges[e];
        float2 x = E2[p.x * 32 + lane];
        float v = __int_as_float(p.y);
        z3.x += v * x.x; z3.y += v * x.y;
    }
    return make_float2(z0.x + z1.x + z2.x + z3.x, z0.y + z1.y + z2.y + z3.y);
}

// gamma[w] = dot(acc(u), acc(NUSERS+i)) / 16
__global__ __launch_bounds__(256) void k_gamma(const int* __restrict__ users,
                                               const int* __restrict__ items,
                                               float* __restrict__ out) {
    int w    = (blockIdx.x * 256 + threadIdx.x) >> 5;   // warp per output pair
    int lane = threadIdx.x & 31;
    if (w >= 4096) return;
    float2 a = node_acc(users[w],          lane);
    float2 b = node_acc(NUSERS + items[w], lane);
    float s = a.x * b.x + a.y * b.y;
    #pragma unroll
    for (int o = 16; o; o >>= 1) s += __shfl_xor_sync(0xffffffffu, s, o);
    if (lane == 0) out[w] = s * (1.0f / 16.0f);
}

extern "C" void kernel_launch(void* const* d_in, const int* in_sizes, int n_in,
                              void* d_out, int out_size) {
    const int*   users = (const int*)  d_in[0];
    const int*   items = (const int*)  d_in[1];
    const int*   er    = (const int*)  d_in[2];
    const int*   ec    = (const int*)  d_in[3];
    const float* ev    = (const float*)d_in[4];
    const float* ue    = (const float*)d_in[5];
    const float* ie    = (const float*)d_in[6];
    float* out = (float*)d_out;

    const int INIT_BLOCKS = (NV4 + 255) / 256;            // 9375
    const int PROP_BLOCKS = (NNODES * 8 + 255) / 256;     // 4688 (8 lanes/row)
    const int REO_BLOCKS  = (NEDGES + 1023) / 1024;       // 1172 (4 edges/thread)

    k_inithist<<<INIT_BLOCKS, 256>>>(ue, ie, er);
    k_scan1<<<NBLK, SCAN_B>>>();                          // scan2 fused (last block)
    k_reorder<<<REO_BLOCKS, 256>>>(er, ec, ev);
    k_prop0<<<PROP_BLOCKS, 256>>>();                      // captured by ncu (-s5 -c1)
    k_prop1<<<PROP_BLOCKS, 256>>>();
    k_gamma<<<4096 / 8, 256>>>(users, items, out);
}

// round 12
// speedup vs baseline: 2.9587x; 1.2944x over previous
#include <cuda_runtime.h>
#include <cuda_fp16.h>

#define NUSERS 100000
#define NITEMS 50000
#define NNODES 150000
#define NEDGES 1200000
#define NH4    (NNODES * 8)         // uint4 (8-half) slots per fp16 buffer
#define SCAN_B 1024
#define NBLK   ((NNODES + SCAN_B - 1) / SCAN_B)   // 147

// fp16 embedding buffers (3 x 19.2 MB -> whole working set L2-resident) + CSR.
// Zero-state protocol (every call leaves arrays zeroed for the next call):
// g_cnt zeroed by k_reorder epilogue, g_pos by k_prop0 epilogue, g_done by
// k_scan1's finalizer block. First call relies on static zero-init.
__device__ __align__(16) uint4 g_h0[NH4];
__device__ __align__(16) uint4 g_h1[NH4];
__device__ __align__(16) uint4 g_h2[NH4];
__device__ int  g_cnt[NNODES];
__device__ int  g_pos[NNODES];
__device__ int  g_rowptr[NNODES + 1];
__device__ int  g_bsum[NBLK];
__device__ int  g_done;
__device__ __align__(8) int2 g_edges[NEDGES];   // {col, __float_as_int(0.8*val)}

// ---- fp16 pack/unpack helpers (fp32 accumulation everywhere) ----
__device__ __forceinline__ void unpack8(uint4 x, float* f) {
    float2 a = __half22float2(*reinterpret_cast<__half2*>(&x.x));
    float2 b = __half22float2(*reinterpret_cast<__half2*>(&x.y));
    float2 c = __half22float2(*reinterpret_cast<__half2*>(&x.z));
    float2 d = __half22float2(*reinterpret_cast<__half2*>(&x.w));
    f[0] = a.x; f[1] = a.y; f[2] = b.x; f[3] = b.y;
    f[4] = c.x; f[5] = c.y; f[6] = d.x; f[7] = d.y;
}
__device__ __forceinline__ uint4 pack8(const float* f) {
    uint4 x;
    *reinterpret_cast<__half2*>(&x.x) = __floats2half2_rn(f[0], f[1]);
    *reinterpret_cast<__half2*>(&x.y) = __floats2half2_rn(f[2], f[3]);
    *reinterpret_cast<__half2*>(&x.z) = __floats2half2_rn(f[4], f[5]);
    *reinterpret_cast<__half2*>(&x.w) = __floats2half2_rn(f[6], f[7]);
    return x;
}
__device__ __forceinline__ void fma8(float* s, uint4 x, float v) {
    float f[8]; unpack8(x, f);
    #pragma unroll
    for (int j = 0; j < 8; j++) s[j] += v * f[j];
}

// h0 = fp16(concat(user_emb, item_emb)), fused with the row histogram.
// g_cnt is already zero at entry (static init / previous call's epilogue).
__global__ __launch_bounds__(256) void k_inithist(const float* __restrict__ ue,
                                                  const float* __restrict__ ie,
                                                  const int* __restrict__ er) {
    int i = blockIdx.x * 256 + threadIdx.x;
    if (i < NEDGES) atomicAdd(&g_cnt[er[i]], 1);
    if (i >= NH4) return;
    const float4* src = (i < NUSERS * 8) ? (const float4*)ue : (const float4*)ie;
    int j = (i < NUSERS * 8) ? i : i - NUSERS * 8;
    float4 p = src[2 * j];
    float4 q = src[2 * j + 1];
    float f[8] = {p.x, p.y, p.z, p.w, q.x, q.y, q.z, q.w};
    g_h0[i] = pack8(f);
}

// Coalesced per-block scan of g_cnt -> g_rowptr; fused block-total scan
// (last-arriving block converts g_bsum to exclusive prefix, resets g_done).
__global__ __launch_bounds__(SCAN_B) void k_scan1() {
    __shared__ int sh[SCAN_B];
    __shared__ int s_last;
    int idx = blockIdx.x * SCAN_B + threadIdx.x;
    int v = (idx < NNODES) ? g_cnt[idx] : 0;
    sh[threadIdx.x] = v;
    __syncthreads();
    #pragma unroll
    for (int o = 1; o < SCAN_B; o <<= 1) {
        int t = (threadIdx.x >= o) ? sh[threadIdx.x - o] : 0;
        __syncthreads();
        sh[threadIdx.x] += t;
        __syncthreads();
    }
    int incl = sh[threadIdx.x];
    if (idx <= NNODES) g_rowptr[idx] = incl - v;
    if (threadIdx.x == SCAN_B - 1) g_bsum[blockIdx.x] = incl;

    __threadfence();
    if (threadIdx.x == 0) s_last = (atomicAdd(&g_done, 1) == NBLK - 1);
    __syncthreads();
    if (s_last) {
        int i = threadIdx.x;
        int bv = (i < NBLK) ? g_bsum[i] : 0;
        sh[i] = bv;
        __syncthreads();
        #pragma unroll
        for (int o = 1; o < SCAN_B; o <<= 1) {
            int t = (i >= o) ? sh[i - o] : 0;
            __syncthreads();
            sh[i] += t;
            __syncthreads();
        }
        if (i < NBLK) g_bsum[i] = sh[i] - bv;
        if (i == 0) g_done = 0;
    }
}

__device__ __forceinline__ void row_range(int row, int& beg, int& end) {
    beg = g_rowptr[row]     + g_bsum[row >> 10];
    end = g_rowptr[row + 1] + g_bsum[(row + 1) >> 10];
}

// Place edges into row segments, 4 edges/thread; epilogue re-zeroes g_cnt.
__global__ __launch_bounds__(256) void k_reorder(const int* __restrict__ er,
                                                 const int* __restrict__ ec,
                                                 const float* __restrict__ ev) {
    int t = blockIdx.x * 256 + threadIdx.x;
    int b = blockIdx.x * 1024 + threadIdx.x;
    #pragma unroll
    for (int j = 0; j < 4; j++) {
        int e = b + j * 256;
        if (e < NEDGES) {
            int row  = er[e];
            int base = g_rowptr[row] + g_bsum[row >> 10];
            int pos  = base + atomicAdd(&g_pos[row], 1);
            g_edges[pos] = make_int2(ec[e], __float_as_int(ev[e] * 0.8f));
        }
    }
    if (t < NNODES) g_cnt[t] = 0;
}

// dst[row] = fp16( 0.2*src[row] + sum 0.8v*src[col] )
// 8 lanes/row; one uint4 (8 halves) per lane per gather -> each 8-lane group
// reads one dense 128B line (the whole row). fp32 accumulation in registers.
template <int ZERO_POS>
__device__ __forceinline__ void prop_body(const uint4* __restrict__ src,
                                          uint4* __restrict__ dst) {
    int t = blockIdx.x * 256 + threadIdx.x;        // NNODES*8 threads
    if (ZERO_POS && t < NNODES) g_pos[t] = 0;
    int row = t >> 3;
    if (row >= NNODES) return;
    int sub  = t & 7;
    int base = row * 8 + sub;
    int beg, end; row_range(row, beg, end);

    float s[8];
    {
        float f[8]; unpack8(src[base], f);
        #pragma unroll
        for (int j = 0; j < 8; j++) s[j] = 0.2f * f[j];
    }

    int e  = beg;
    int n4 = beg + ((end - beg) & ~3);
    for (; e < n4; e += 4) {                       // 4 gathers + 4 edge loads in flight
        int2 p0 = g_edges[e];
        int2 p1 = g_edges[e + 1];
        int2 p2 = g_edges[e + 2];
        int2 p3 = g_edges[e + 3];
        uint4 x0 = src[p0.x * 8 + sub];
        uint4 x1 = src[p1.x * 8 + sub];
        uint4 x2 = src[p2.x * 8 + sub];
        uint4 x3 = src[p3.x * 8 + sub];
        fma8(s, x0, __int_as_float(p0.y));
        fma8(s, x1, __int_as_float(p1.y));
        fma8(s, x2, __int_as_float(p2.y));
        fma8(s, x3, __int_as_float(p3.y));
    }
    for (; e < end; e++) {
        int2 p = g_edges[e];
        uint4 x = src[p.x * 8 + sub];
        fma8(s, x, __int_as_float(p.y));
    }
    dst[base] = pack8(s);
}

__global__ __launch_bounds__(256) void k_prop0() { prop_body<1>(g_h0, g_h1); }
__global__ __launch_bounds__(256) void k_prop1() { prop_body<0>(g_h1, g_h2); }

// acc(n) = e0+e1+e2+e3 (fp32), e3 on the fly from fp16 e2; one half2 per lane.
__device__ __forceinline__ float2 node_acc(int n, int lane) {
    const unsigned* __restrict__ H0 = (const unsigned*)g_h0;
    const unsigned* __restrict__ H1 = (const unsigned*)g_h1;
    const unsigned* __restrict__ H2 = (const unsigned*)g_h2;
    int idx = n * 32 + lane;
    float2 z0 = __half22float2(*(const __half2*)&H0[idx]);
    float2 z1 = __half22float2(*(const __half2*)&H1[idx]);
    float2 z2 = __half22float2(*(const __half2*)&H2[idx]);
    float2 z3 = make_float2(0.2f * z2.x, 0.2f * z2.y);
    int beg, end; row_range(n, beg, end);
    int e  = beg;
    int n4 = beg + ((end - beg) & ~3);
    for (; e < n4; e += 4) {
        int2 p0 = g_edges[e];
        int2 p1 = g_edges[e + 1];
        int2 p2 = g_edges[e + 2];
        int2 p3 = g_edges[e + 3];
        float2 x0 = __half22float2(*(const __half2*)&H2[p0.x * 32 + lane]);
        float2 x1 = __half22float2(*(const __half2*)&H2[p1.x * 32 + lane]);
        float2 x2 = __half22float2(*(const __half2*)&H2[p2.x * 32 + lane]);
        float2 x3 = __half22float2(*(const __half2*)&H2[p3.x * 32 + lane]);
        z3.x += __int_as_float(p0.y) * x0.x; z3.y += __int_as_float(p0.y) * x0.y;
        z3.x += __int_as_float(p1.y) * x1.x; z3.y += __int_as_float(p1.y) * x1.y;
        z3.x += __int_as_float(p2.y) * x2.x; z3.y += __int_as_float(p2.y) * x2.y;
        z3.x += __int_as_float(p3.y) * x3.x; z3.y += __int_as_float(p3.y) * x3.y;
    }
    for (; e < end; e++) {
        int2 p = g_edges[e];
        float2 x = __half22float2(*(const __half2*)&H2[p.x * 32 + lane]);
        float v = __int_as_float(p.y);
        z3.x += v * x.x; z3.y += v * x.y;
    }
    return make_float2(z0.x + z1.x + z2.x + z3.x, z0.y + z1.y + z2.y + z3.y);
}

// gamma[w] = dot(acc(u), acc(NUSERS+i)) / 16
__global__ __launch_bounds__(256) void k_gamma(const int* __restrict__ users,
                                               const int* __restrict__ items,
                                               float* __restrict__ out) {
    int w    = (blockIdx.x * 256 + threadIdx.x) >> 5;
    int lane = threadIdx.x & 31;
    if (w >= 4096) return;
    float2 a = node_acc(users[w],          lane);
    float2 b = node_acc(NUSERS + items[w], lane);
    float s = a.x * b.x + a.y * b.y;
    #pragma unroll
    for (int o = 16; o; o >>= 1) s += __shfl_xor_sync(0xffffffffu, s, o);
    if (lane == 0) out[w] = s * (1.0f / 16.0f);
}

extern "C" void kernel_launch(void* const* d_in, const int* in_sizes, int n_in,
                              void* d_out, int out_size) {
    const int*   users = (const int*)  d_in[0];
    const int*   items = (const int*)  d_in[1];
    const int*   er    = (const int*)  d_in[2];
    const int*   ec    = (const int*)  d_in[3];
    const float* ev    = (const float*)d_in[4];
    const float* ue    = (const float*)d_in[5];
    const float* ie    = (const float*)d_in[6];
    float* out = (float*)d_out;

    const int INIT_BLOCKS = (NH4 + 255) / 256;            // 4688 (covers NEDGES too)
    const int PROP_BLOCKS = (NNODES * 8 + 255) / 256;     // 4688
    const int REO_BLOCKS  = (NEDGES + 1023) / 1024;       // 1172

    k_inithist<<<INIT_BLOCKS, 256>>>(ue, ie, er);
    k_scan1<<<NBLK, SCAN_B>>>();
    k_reorder<<<REO_BLOCKS, 256>>>(er, ec, ev);
    k_prop0<<<PROP_BLOCKS, 256>>>();                      // ncu capture slot
    k_prop1<<<PROP_BLOCKS, 256>>>();
    k_gamma<<<4096 / 8, 256>>>(users, items, out);
}